// round 6
// baseline (speedup 1.0000x reference)
#include <cuda_runtime.h>
#include <cuda_bf16.h>
#include <cstdint>

#define BATCH 16
#define C_IN  256
#define HW    4096
#define C8    32
#define C2    128
#define MPOOL 1024
#define CPROJ 192   // 32 theta + 32 phi + 128 g

// ---------------- scratch (device globals; no allocation allowed) ----------
__device__ float         d_theta[BATCH * HW * C8];     // [b][n][k]  (tf32-rounded)
__device__ float         d_phi[BATCH * C8 * MPOOL];    // [b][k][m]  (tf32-rounded)
__device__ __nv_bfloat16 d_gT[BATCH * C2 * MPOOL];     // [b][d][m]
__device__ __nv_bfloat16 d_ag[BATCH * HW * C2];        // [b][n][d]
__device__ __nv_bfloat16 d_wfb[C_IN * C2];             // bf16 copy of w_final

// ---------------- helpers ---------------------------------------------------
__device__ __forceinline__ float tf32r(float f) {
    uint32_t u;
    asm("cvt.rna.tf32.f32 %0, %1;" : "=r"(u) : "f"(f));
    return __uint_as_float(u);
}

__device__ __forceinline__ float ex2(float x) {
    float y;
    asm("ex2.approx.ftz.f32 %0, %1;" : "=f"(y) : "f"(x));
    return y;
}

__device__ __forceinline__ void mma_tf32(float* d, const uint32_t* a,
                                         uint32_t b0, uint32_t b1) {
    asm volatile(
        "mma.sync.aligned.m16n8k8.row.col.f32.tf32.tf32.f32 "
        "{%0,%1,%2,%3}, {%4,%5,%6,%7}, {%8,%9}, {%0,%1,%2,%3};"
        : "+f"(d[0]), "+f"(d[1]), "+f"(d[2]), "+f"(d[3])
        : "r"(a[0]), "r"(a[1]), "r"(a[2]), "r"(a[3]), "r"(b0), "r"(b1));
}

__device__ __forceinline__ void mma_bf16(float* d, const uint32_t* a,
                                         uint32_t b0, uint32_t b1) {
    asm volatile(
        "mma.sync.aligned.m16n8k16.row.col.f32.bf16.bf16.f32 "
        "{%0,%1,%2,%3}, {%4,%5,%6,%7}, {%8,%9}, {%0,%1,%2,%3};"
        : "+f"(d[0]), "+f"(d[1]), "+f"(d[2]), "+f"(d[3])
        : "r"(a[0]), "r"(a[1]), "r"(a[2]), "r"(a[3]), "r"(b0), "r"(b1));
}

__device__ __forceinline__ void ldsm_x4(uint32_t& r0, uint32_t& r1,
                                        uint32_t& r2, uint32_t& r3, uint32_t a) {
    asm volatile("ldmatrix.sync.aligned.m8n8.x4.shared.b16 {%0,%1,%2,%3}, [%4];"
                 : "=r"(r0), "=r"(r1), "=r"(r2), "=r"(r3) : "r"(a));
}
__device__ __forceinline__ void ldsm_x2(uint32_t& r0, uint32_t& r1, uint32_t a) {
    asm volatile("ldmatrix.sync.aligned.m8n8.x2.shared.b16 {%0,%1}, [%2];"
                 : "=r"(r0), "=r"(r1) : "r"(a));
}

__device__ __forceinline__ uint32_t pack_bf16(float a, float b) {
    __nv_bfloat162 h = __floats2bfloat162_rn(a, b);
    return *reinterpret_cast<uint32_t*>(&h);
}

__device__ __forceinline__ void cp16(uint32_t smem, const void* g) {
    asm volatile("cp.async.cg.shared.global [%0], [%1], 16;\n"
                 :: "r"(smem), "l"(g));
}
__device__ __forceinline__ void cp_commit() {
    asm volatile("cp.async.commit_group;\n");
}
template <int N>
__device__ __forceinline__ void cp_wait() {
    asm volatile("cp.async.wait_group %0;\n" :: "n"(N));
}

#define LOG2E 1.4426950408889634f

// =============================================================================
// K0: w_final fp32 -> bf16 (one-time, tiny)
// =============================================================================
__global__ void wfconv_kernel(const float* __restrict__ wf) {
    int i = blockIdx.x * 256 + threadIdx.x;
    d_wfb[i] = __float2bfloat16(wf[i]);
}

// =============================================================================
// K1: projection GEMM + fused 2x2 maxpool, 3-stage cp.async pipeline.
// 512 threads, 16 warps (4m x 4n), warp tile 48x32. tf32 mma.
// =============================================================================
#define PJ_A_F   (192 * 40)
#define PJ_B_F   (32 * 132)
#define PJ_STAGE (PJ_A_F + PJ_B_F)           // floats
#define PJ_SMEM_B (3 * PJ_STAGE * 4)         // 142848 bytes (>= ytile 160*132*4)

__device__ __forceinline__ void proj_load(uint32_t a_s, uint32_t b_s,
                                          const float* wth, const float* wph,
                                          const float* wg, const float* xb,
                                          int kc, int p0, int tid) {
#pragma unroll
    for (int i = 0; i < 3; i++) {        // A: 192 rows x 32 floats
        int c = tid + i * 512;
        int r = c >> 3, q = c & 7;
        const float* src = (r < 32) ? wth + r * 256
                        : (r < 64) ? wph + (r - 32) * 256
                                   : wg + (r - 64) * 256;
        cp16(a_s + (r * 40 + q * 4) * 4, src + kc * 32 + q * 4);
    }
#pragma unroll
    for (int i = 0; i < 2; i++) {        // B: 32 rows x 128 floats
        int c = tid + i * 512;
        int kk = c >> 5, j4 = c & 31;
        cp16(b_s + (kk * 132 + j4 * 4) * 4,
             xb + (size_t)(kc * 32 + kk) * HW + p0 + j4 * 4);
    }
}

__global__ __launch_bounds__(512, 1)
void proj_kernel(const float* __restrict__ x,
                 const float* __restrict__ wth,
                 const float* __restrict__ wph,
                 const float* __restrict__ wg) {
    extern __shared__ float sm[];
    const uint32_t sm_u = (uint32_t)__cvta_generic_to_shared(sm);

    const int b   = blockIdx.y;
    const int p0  = blockIdx.x * 128;
    const int tid = threadIdx.x;
    const int w   = tid >> 5, lane = tid & 31;
    const int g   = lane >> 2, tig = lane & 3;
    const int wm  = w >> 2, wn = w & 3;
    const int m0w = wm * 48, n0w = wn * 32;

    float acc[3][4][4];
#pragma unroll
    for (int mt = 0; mt < 3; mt++)
#pragma unroll
        for (int nt = 0; nt < 4; nt++)
#pragma unroll
            for (int j = 0; j < 4; j++) acc[mt][nt][j] = 0.f;

    const float* xb = x + (size_t)b * C_IN * HW;

    proj_load(sm_u, sm_u + PJ_A_F * 4, wth, wph, wg, xb, 0, p0, tid);
    cp_commit();
    proj_load(sm_u + PJ_STAGE * 4, sm_u + (PJ_STAGE + PJ_A_F) * 4,
              wth, wph, wg, xb, 1, p0, tid);
    cp_commit();

    for (int kc = 0; kc < 8; kc++) {
        const int cur = kc % 3;
        if (kc + 2 < 8) {
            const int nst = (kc + 2) % 3;
            proj_load(sm_u + nst * PJ_STAGE * 4,
                      sm_u + (nst * PJ_STAGE + PJ_A_F) * 4,
                      wth, wph, wg, xb, kc + 2, p0, tid);
            cp_commit();
            cp_wait<2>();
        } else if (kc + 1 < 8) {
            cp_wait<1>();
        } else {
            cp_wait<0>();
        }
        __syncthreads();

        const float* Ac = sm + cur * PJ_STAGE;
        const float* Bc = sm + cur * PJ_STAGE + PJ_A_F;
#pragma unroll
        for (int ks = 0; ks < 4; ks++) {
            uint32_t a[3][4];
#pragma unroll
            for (int mt = 0; mt < 3; mt++) {
                int r = m0w + mt * 16;
                a[mt][0] = __float_as_uint(Ac[(r + g)     * 40 + ks * 8 + tig]);
                a[mt][1] = __float_as_uint(Ac[(r + g + 8) * 40 + ks * 8 + tig]);
                a[mt][2] = __float_as_uint(Ac[(r + g)     * 40 + ks * 8 + tig + 4]);
                a[mt][3] = __float_as_uint(Ac[(r + g + 8) * 40 + ks * 8 + tig + 4]);
            }
#pragma unroll
            for (int nt = 0; nt < 4; nt++) {
                uint32_t b0 = __float_as_uint(Bc[(ks * 8 + tig)     * 132 + n0w + nt * 8 + g]);
                uint32_t b1 = __float_as_uint(Bc[(ks * 8 + tig + 4) * 132 + n0w + nt * 8 + g]);
#pragma unroll
                for (int mt = 0; mt < 3; mt++) mma_tf32(acc[mt][nt], a[mt], b0, b1);
            }
        }
        __syncthreads();
    }

    // ---- epilogue: theta direct (transposed, rna); phi/g into smem ytile ----
    float* ytile = sm;   // 160 ch x 132 floats; staging buffers dead
    float* thb = d_theta + (size_t)b * HW * C8;
#pragma unroll
    for (int mt = 0; mt < 3; mt++)
#pragma unroll
        for (int nt = 0; nt < 4; nt++) {
            int pl = n0w + nt * 8 + tig * 2;
            int p  = p0 + pl;
            int c0 = m0w + mt * 16 + g;
            int c1 = c0 + 8;
            if (c0 < 32) {
                thb[(size_t)p * 32 + c0]       = tf32r(acc[mt][nt][0]);
                thb[(size_t)(p + 1) * 32 + c0] = tf32r(acc[mt][nt][1]);
                thb[(size_t)p * 32 + c1]       = tf32r(acc[mt][nt][2]);
                thb[(size_t)(p + 1) * 32 + c1] = tf32r(acc[mt][nt][3]);
            } else {
                ytile[(c0 - 32) * 132 + pl]     = acc[mt][nt][0];
                ytile[(c0 - 32) * 132 + pl + 1] = acc[mt][nt][1];
                ytile[(c1 - 32) * 132 + pl]     = acc[mt][nt][2];
                ytile[(c1 - 32) * 132 + pl + 1] = acc[mt][nt][3];
            }
        }
    __syncthreads();

    const int m0 = (p0 >> 2);
#pragma unroll
    for (int i = 0; i < 10; i++) {
        int idx = tid + i * 512;
        int ch = idx >> 5, wp = idx & 31;
        const float* r0 = &ytile[ch * 132 + wp * 2];
        float v = fmaxf(fmaxf(r0[0], r0[1]), fmaxf(r0[64], r0[65]));
        if (ch < 32)
            d_phi[((size_t)b * 32 + ch) * MPOOL + m0 + wp] = tf32r(v);
        else
            d_gT[((size_t)b * C2 + (ch - 32)) * MPOOL + m0 + wp] = __float2bfloat16(v);
    }
}

// =============================================================================
// K2: fused flash attention (no online max), 3-stage cp.async pipeline.
// 512 threads, 16 warps = 8 q-groups x 2 d-groups. Warp: 16q x 64d.
// =============================================================================
#define KB       64
#define NTILE    (MPOOL / KB)        // 16
#define PH_STR   68
#define G_STR    72
#define PH_BYTES (32 * PH_STR * 4)   // 8704
#define G_BYTES  (128 * G_STR * 2)   // 18432
#define K2_STAGE (PH_BYTES + G_BYTES)
#define K2_SMEM  (3 * K2_STAGE)      // 81408

__device__ __forceinline__ void attn_load_tile(uint32_t stage_base,
                                               const float* phb,
                                               const __nv_bfloat16* gTb,
                                               int mb, int tid) {
    const uint32_t ph_s = stage_base;
    const uint32_t g_s  = stage_base + PH_BYTES;
    {   // phi: 32 rows x 64 floats = 512 x 16B
        int r = tid >> 4, col = tid & 15;
        cp16(ph_s + r * (PH_STR * 4) + col * 16,
             phb + (size_t)r * MPOOL + mb + col * 4);
    }
#pragma unroll
    for (int i = 0; i < 2; i++) {   // g: 128 rows x 64 bf16 = 1024 x 16B
        int c = tid + i * 512;
        int r = c >> 3, col = c & 7;
        cp16(g_s + r * (G_STR * 2) + col * 16,
             gTb + (size_t)r * MPOOL + mb + col * 8);
    }
}

__global__ __launch_bounds__(512, 1)
void attn_kernel() {
    extern __shared__ char smraw[];
    const uint32_t smem_u32 = (uint32_t)__cvta_generic_to_shared(smraw);

    const int b   = blockIdx.y, qt = blockIdx.x;
    const int tid = threadIdx.x;
    const int w   = tid >> 5, lane = tid & 31;
    const int g   = lane >> 2, tig = lane & 3;
    const int qg  = w >> 1, dg = w & 1;
    const int n0  = qt * 128 + qg * 16;
    const int d0  = dg * 64;

    const float*         phb = d_phi + (size_t)b * 32 * MPOOL;
    const __nv_bfloat16* gTb = d_gT + (size_t)b * C2 * MPOOL;

    // persistent theta A-fragments (tf32); same for both d-halves of a q-group
    uint32_t at[4][4];
    {
        const float* th = d_theta + ((size_t)b * HW + n0) * 32;
#pragma unroll
        for (int ks = 0; ks < 4; ks++) {
            at[ks][0] = __float_as_uint(th[g * 32       + ks * 8 + tig]);
            at[ks][1] = __float_as_uint(th[(g + 8) * 32 + ks * 8 + tig]);
            at[ks][2] = __float_as_uint(th[g * 32       + ks * 8 + tig + 4]);
            at[ks][3] = __float_as_uint(th[(g + 8) * 32 + ks * 8 + tig + 4]);
        }
    }

    float O[8][4];
#pragma unroll
    for (int df = 0; df < 8; df++)
#pragma unroll
        for (int j = 0; j < 4; j++) O[df][j] = 0.f;
    float lsum0 = 0.f, lsum1 = 0.f;

    attn_load_tile(smem_u32, phb, gTb, 0, tid);
    cp_commit();
    attn_load_tile(smem_u32 + K2_STAGE, phb, gTb, KB, tid);
    cp_commit();

    for (int kb = 0; kb < NTILE; kb++) {
        const int cur = kb % 3;
        if (kb + 2 < NTILE) {
            attn_load_tile(smem_u32 + ((kb + 2) % 3) * K2_STAGE,
                           phb, gTb, (kb + 2) * KB, tid);
            cp_commit();
            cp_wait<2>();
        } else if (kb + 1 < NTILE) {
            cp_wait<1>();
        } else {
            cp_wait<0>();
        }
        __syncthreads();

        const uint32_t phc = smem_u32 + cur * K2_STAGE;
        const uint32_t gc  = phc + PH_BYTES;

        // ---- QK scores: S (16 q x 64 keys), tf32 (computed per d-half) ----
        float S[8][4];
#pragma unroll
        for (int nf = 0; nf < 8; nf++)
            S[nf][0] = S[nf][1] = S[nf][2] = S[nf][3] = 0.f;
#pragma unroll
        for (int ks = 0; ks < 4; ks++) {
#pragma unroll
            for (int nf = 0; nf < 8; nf++) {
                uint32_t b0, b1;
                uint32_t a0 = phc + ((ks * 8 + tig) * PH_STR + nf * 8 + g) * 4;
                asm volatile("ld.shared.b32 %0, [%1];" : "=r"(b0) : "r"(a0));
                asm volatile("ld.shared.b32 %0, [%1];" : "=r"(b1) : "r"(a0 + 4 * PH_STR * 4));
                mma_tf32(S[nf], at[ks], b0, b1);
            }
        }

#pragma unroll
        for (int nf = 0; nf < 8; nf++) {
            S[nf][0] = ex2(S[nf][0] * LOG2E);
            S[nf][1] = ex2(S[nf][1] * LOG2E);
            S[nf][2] = ex2(S[nf][2] * LOG2E);
            S[nf][3] = ex2(S[nf][3] * LOG2E);
            lsum0 += S[nf][0] + S[nf][1];
            lsum1 += S[nf][2] + S[nf][3];
        }

        uint32_t P[4][4];
#pragma unroll
        for (int kf = 0; kf < 4; kf++) {
            P[kf][0] = pack_bf16(S[2 * kf][0],     S[2 * kf][1]);
            P[kf][1] = pack_bf16(S[2 * kf][2],     S[2 * kf][3]);
            P[kf][2] = pack_bf16(S[2 * kf + 1][0], S[2 * kf + 1][1]);
            P[kf][3] = pack_bf16(S[2 * kf + 1][2], S[2 * kf + 1][3]);
        }

        // ---- PV via ldmatrix.x4 on this warp's 64-d half ----
#pragma unroll
        for (int pair = 0; pair < 2; pair++) {
#pragma unroll
            for (int df = 0; df < 8; df++) {
                uint32_t r0, r1, r2, r3;
                uint32_t addr = gc +
                    ((d0 + df * 8 + (lane & 7)) * G_STR + pair * 32 + (lane >> 3) * 8) * 2;
                ldsm_x4(r0, r1, r2, r3, addr);
                mma_bf16(O[df], P[2 * pair],     r0, r1);
                mma_bf16(O[df], P[2 * pair + 1], r2, r3);
            }
        }
        __syncthreads();
    }

    lsum0 += __shfl_xor_sync(0xffffffffu, lsum0, 1);
    lsum0 += __shfl_xor_sync(0xffffffffu, lsum0, 2);
    lsum1 += __shfl_xor_sync(0xffffffffu, lsum1, 1);
    lsum1 += __shfl_xor_sync(0xffffffffu, lsum1, 2);
    const float i0 = 1.f / lsum0, i1 = 1.f / lsum1;

    __nv_bfloat16* agb = d_ag + ((size_t)b * HW + n0) * C2;
#pragma unroll
    for (int df = 0; df < 8; df++) {
        uint32_t v0 = pack_bf16(O[df][0] * i0, O[df][1] * i0);
        uint32_t v1 = pack_bf16(O[df][2] * i1, O[df][3] * i1);
        *reinterpret_cast<uint32_t*>(&agb[g * C2 + d0 + df * 8 + tig * 2])       = v0;
        *reinterpret_cast<uint32_t*>(&agb[(g + 8) * C2 + d0 + df * 8 + tig * 2]) = v1;
    }
}

// =============================================================================
// K3: out = sigma * (w_final @ attn_g^T) + x
// block 128co x 64p, 3 CTAs/SM (round-4 best config), bf16 wf precomputed.
// =============================================================================
#define F_STR    136
#define F_ABYTES (128 * F_STR * 2)      // 34816
#define F_BBYTES (64 * F_STR * 2)       // 17408
#define F_SMEM   (F_ABYTES + F_BBYTES)  // 52224

__global__ __launch_bounds__(256, 3)
void final_kernel(const float* __restrict__ x,
                  const float* __restrict__ sigp,
                  float* __restrict__ out) {
    extern __shared__ char smraw[];
    const uint32_t as_u = (uint32_t)__cvta_generic_to_shared(smraw);
    const uint32_t bs_u = as_u + F_ABYTES;

    const int b   = blockIdx.y;
    const int co0 = (blockIdx.x & 1) * 128;
    const int p0  = (blockIdx.x >> 1) * 64;
    const int tid = threadIdx.x;
    const int w   = tid >> 5, lane = tid & 31;
    const int g   = lane >> 2, tig = lane & 3;
    const int wm  = w >> 1, wn = w & 1;
    const int cw  = wm * 32, pw = wn * 32;

    const __nv_bfloat16* wfb = d_wfb + (size_t)co0 * C2;
#pragma unroll
    for (int i = 0; i < 8; i++) {
        int c = tid + i * 256;
        int r = c >> 4, q = c & 15;
        cp16(as_u + (r * F_STR + q * 8) * 2, wfb + (size_t)r * C2 + q * 8);
    }
    const __nv_bfloat16* agb = d_ag + ((size_t)b * HW + p0) * C2;
#pragma unroll
    for (int i = 0; i < 4; i++) {
        int c = tid + i * 256;
        int j = c >> 4, q = c & 15;
        cp16(bs_u + (j * F_STR + q * 8) * 2, agb + (size_t)j * C2 + q * 8);
    }
    cp_commit();
    cp_wait<0>();
    __syncthreads();

    float acc[2][4][4];
#pragma unroll
    for (int mt = 0; mt < 2; mt++)
#pragma unroll
        for (int nt = 0; nt < 4; nt++)
#pragma unroll
            for (int j = 0; j < 4; j++) acc[mt][nt][j] = 0.f;

#pragma unroll
    for (int k16 = 0; k16 < 8; k16++) {
        uint32_t a[2][4];
#pragma unroll
        for (int mt = 0; mt < 2; mt++) {
            uint32_t addr = as_u +
                ((cw + mt * 16 + (lane & 15)) * F_STR + k16 * 16 + (lane >> 4) * 8) * 2;
            ldsm_x4(a[mt][0], a[mt][1], a[mt][2], a[mt][3], addr);
        }
        uint32_t bq[4][2];
#pragma unroll
        for (int nt = 0; nt < 4; nt++) {
            uint32_t addr = bs_u +
                ((pw + nt * 8 + (lane & 7)) * F_STR + k16 * 16 + ((lane >> 3) & 1) * 8) * 2;
            ldsm_x2(bq[nt][0], bq[nt][1], addr);
        }
#pragma unroll
        for (int nt = 0; nt < 4; nt++)
#pragma unroll
            for (int mt = 0; mt < 2; mt++)
                mma_bf16(acc[mt][nt], a[mt], bq[nt][0], bq[nt][1]);
    }

    const float sig = *sigp;
#pragma unroll
    for (int mt = 0; mt < 2; mt++)
#pragma unroll
        for (int nt = 0; nt < 4; nt++) {
            int co = co0 + cw + mt * 16 + g;
            int p  = p0 + pw + nt * 8 + tig * 2;
            {
                size_t off = ((size_t)b * 256 + co) * HW + p;
                float2 xv = *reinterpret_cast<const float2*>(&x[off]);
                float2 ov = make_float2(sig * acc[mt][nt][0] + xv.x,
                                        sig * acc[mt][nt][1] + xv.y);
                *reinterpret_cast<float2*>(&out[off]) = ov;
            }
            {
                size_t off = ((size_t)b * 256 + co + 8) * HW + p;
                float2 xv = *reinterpret_cast<const float2*>(&x[off]);
                float2 ov = make_float2(sig * acc[mt][nt][2] + xv.x,
                                        sig * acc[mt][nt][3] + xv.y);
                *reinterpret_cast<float2*>(&out[off]) = ov;
            }
        }
}

// =============================================================================
extern "C" void kernel_launch(void* const* d_in, const int* in_sizes, int n_in,
                              void* d_out, int out_size) {
    (void)in_sizes; (void)n_in; (void)out_size;
    const float* x    = (const float*)d_in[0];
    const float* wth  = (const float*)d_in[1];
    const float* wph  = (const float*)d_in[2];
    const float* wg   = (const float*)d_in[3];
    const float* wf   = (const float*)d_in[4];
    const float* sig  = (const float*)d_in[5];
    float*       out  = (float*)d_out;

    cudaFuncSetAttribute(proj_kernel,
                         cudaFuncAttributeMaxDynamicSharedMemorySize, PJ_SMEM_B);
    cudaFuncSetAttribute(attn_kernel,
                         cudaFuncAttributeMaxDynamicSharedMemorySize, K2_SMEM);
    cudaFuncSetAttribute(final_kernel,
                         cudaFuncAttributeMaxDynamicSharedMemorySize, F_SMEM);

    wfconv_kernel<<<(C_IN * C2) / 256, 256>>>(wf);
    proj_kernel<<<dim3(32, 16), 512, PJ_SMEM_B>>>(x, wth, wph, wg);
    attn_kernel<<<dim3(32, 16), 512, K2_SMEM>>>();
    final_kernel<<<dim3(128, 16), 256, F_SMEM>>>(x, sig, out);
}

// round 7
// speedup vs baseline: 1.2147x; 1.2147x over previous
#include <cuda_runtime.h>
#include <cuda_bf16.h>
#include <cstdint>

#define BATCH 16
#define C_IN  256
#define HW    4096
#define C8    32
#define C2    128
#define MPOOL 1024
#define CPROJ 192   // 32 theta + 32 phi + 128 g

// ---------------- scratch (device globals; no allocation allowed) ----------
__device__ float         d_theta[BATCH * HW * C8];     // [b][n][k]  (tf32-rounded)
__device__ float         d_phi[BATCH * C8 * MPOOL];    // [b][k][m]  (tf32-rounded)
__device__ __nv_bfloat16 d_gT[BATCH * C2 * MPOOL];     // [b][d][m]
__device__ __nv_bfloat16 d_ag[BATCH * HW * C2];        // [b][n][d]
__device__ __nv_bfloat16 d_wfb[C_IN * C2];             // bf16 copy of w_final

// ---------------- helpers ---------------------------------------------------
__device__ __forceinline__ float tf32r(float f) {
    uint32_t u;
    asm("cvt.rna.tf32.f32 %0, %1;" : "=r"(u) : "f"(f));
    return __uint_as_float(u);
}

__device__ __forceinline__ float ex2(float x) {
    float y;
    asm("ex2.approx.ftz.f32 %0, %1;" : "=f"(y) : "f"(x));
    return y;
}

__device__ __forceinline__ void mma_tf32(float* d, const uint32_t* a,
                                         uint32_t b0, uint32_t b1) {
    asm volatile(
        "mma.sync.aligned.m16n8k8.row.col.f32.tf32.tf32.f32 "
        "{%0,%1,%2,%3}, {%4,%5,%6,%7}, {%8,%9}, {%0,%1,%2,%3};"
        : "+f"(d[0]), "+f"(d[1]), "+f"(d[2]), "+f"(d[3])
        : "r"(a[0]), "r"(a[1]), "r"(a[2]), "r"(a[3]), "r"(b0), "r"(b1));
}

__device__ __forceinline__ void mma_bf16(float* d, const uint32_t* a,
                                         uint32_t b0, uint32_t b1) {
    asm volatile(
        "mma.sync.aligned.m16n8k16.row.col.f32.bf16.bf16.f32 "
        "{%0,%1,%2,%3}, {%4,%5,%6,%7}, {%8,%9}, {%0,%1,%2,%3};"
        : "+f"(d[0]), "+f"(d[1]), "+f"(d[2]), "+f"(d[3])
        : "r"(a[0]), "r"(a[1]), "r"(a[2]), "r"(a[3]), "r"(b0), "r"(b1));
}

__device__ __forceinline__ void ldsm_x4(uint32_t& r0, uint32_t& r1,
                                        uint32_t& r2, uint32_t& r3, uint32_t a) {
    asm volatile("ldmatrix.sync.aligned.m8n8.x4.shared.b16 {%0,%1,%2,%3}, [%4];"
                 : "=r"(r0), "=r"(r1), "=r"(r2), "=r"(r3) : "r"(a));
}
__device__ __forceinline__ void ldsm_x2(uint32_t& r0, uint32_t& r1, uint32_t a) {
    asm volatile("ldmatrix.sync.aligned.m8n8.x2.shared.b16 {%0,%1}, [%2];"
                 : "=r"(r0), "=r"(r1) : "r"(a));
}

__device__ __forceinline__ uint32_t pack_bf16(float a, float b) {
    __nv_bfloat162 h = __floats2bfloat162_rn(a, b);
    return *reinterpret_cast<uint32_t*>(&h);
}

__device__ __forceinline__ void cp16(uint32_t smem, const void* g) {
    asm volatile("cp.async.cg.shared.global [%0], [%1], 16;\n"
                 :: "r"(smem), "l"(g));
}
__device__ __forceinline__ void cp_commit() {
    asm volatile("cp.async.commit_group;\n");
}
template <int N>
__device__ __forceinline__ void cp_wait() {
    asm volatile("cp.async.wait_group %0;\n" :: "n"(N));
}

#define LOG2E 1.4426950408889634f

// =============================================================================
// K0: w_final fp32 -> bf16 (one-time, tiny)
// =============================================================================
__global__ void wfconv_kernel(const float* __restrict__ wf) {
    int i = blockIdx.x * 256 + threadIdx.x;
    d_wfb[i] = __float2bfloat16(wf[i]);
}

// =============================================================================
// K1: projection GEMM + fused 2x2 maxpool, 3-stage cp.async pipeline.
// 256 threads, 8 warps (2m x 4n), warp tile 96x32. tf32 mma.  (round-5 best)
// =============================================================================
#define PJ_A_F   (192 * 40)
#define PJ_B_F   (32 * 132)
#define PJ_STAGE (PJ_A_F + PJ_B_F)           // floats
#define PJ_SMEM_B (3 * PJ_STAGE * 4)         // 142848 bytes (>= ytile 160*132*4)

__device__ __forceinline__ void proj_load(uint32_t a_s, uint32_t b_s,
                                          const float* wth, const float* wph,
                                          const float* wg, const float* xb,
                                          int kc, int p0, int tid) {
#pragma unroll
    for (int i = 0; i < 6; i++) {        // A: 192 rows x 32 floats
        int c = tid + i * 256;
        int r = c >> 3, q = c & 7;
        const float* src = (r < 32) ? wth + r * 256
                        : (r < 64) ? wph + (r - 32) * 256
                                   : wg + (r - 64) * 256;
        cp16(a_s + (r * 40 + q * 4) * 4, src + kc * 32 + q * 4);
    }
#pragma unroll
    for (int i = 0; i < 4; i++) {        // B: 32 rows x 128 floats
        int c = tid + i * 256;
        int kk = c >> 5, j4 = c & 31;
        cp16(b_s + (kk * 132 + j4 * 4) * 4,
             xb + (size_t)(kc * 32 + kk) * HW + p0 + j4 * 4);
    }
}

__global__ __launch_bounds__(256, 1)
void proj_kernel(const float* __restrict__ x,
                 const float* __restrict__ wth,
                 const float* __restrict__ wph,
                 const float* __restrict__ wg) {
    extern __shared__ float sm[];
    const uint32_t sm_u = (uint32_t)__cvta_generic_to_shared(sm);

    const int b   = blockIdx.y;
    const int p0  = blockIdx.x * 128;
    const int tid = threadIdx.x;
    const int w   = tid >> 5, lane = tid & 31;
    const int g   = lane >> 2, tig = lane & 3;
    const int wm  = w >> 2, wn = w & 3;
    const int m0w = wm * 96, n0w = wn * 32;

    float acc[6][4][4];
#pragma unroll
    for (int mt = 0; mt < 6; mt++)
#pragma unroll
        for (int nt = 0; nt < 4; nt++)
#pragma unroll
            for (int j = 0; j < 4; j++) acc[mt][nt][j] = 0.f;

    const float* xb = x + (size_t)b * C_IN * HW;

    proj_load(sm_u, sm_u + PJ_A_F * 4, wth, wph, wg, xb, 0, p0, tid);
    cp_commit();
    proj_load(sm_u + PJ_STAGE * 4, sm_u + (PJ_STAGE + PJ_A_F) * 4,
              wth, wph, wg, xb, 1, p0, tid);
    cp_commit();

    for (int kc = 0; kc < 8; kc++) {
        const int cur = kc % 3;
        if (kc + 2 < 8) {
            const int nst = (kc + 2) % 3;
            proj_load(sm_u + nst * PJ_STAGE * 4,
                      sm_u + (nst * PJ_STAGE + PJ_A_F) * 4,
                      wth, wph, wg, xb, kc + 2, p0, tid);
            cp_commit();
            cp_wait<2>();
        } else if (kc + 1 < 8) {
            cp_wait<1>();
        } else {
            cp_wait<0>();
        }
        __syncthreads();

        const float* Ac = sm + cur * PJ_STAGE;
        const float* Bc = sm + cur * PJ_STAGE + PJ_A_F;
#pragma unroll
        for (int ks = 0; ks < 4; ks++) {
            uint32_t a[6][4];
#pragma unroll
            for (int mt = 0; mt < 6; mt++) {
                int r = m0w + mt * 16;
                a[mt][0] = __float_as_uint(Ac[(r + g)     * 40 + ks * 8 + tig]);
                a[mt][1] = __float_as_uint(Ac[(r + g + 8) * 40 + ks * 8 + tig]);
                a[mt][2] = __float_as_uint(Ac[(r + g)     * 40 + ks * 8 + tig + 4]);
                a[mt][3] = __float_as_uint(Ac[(r + g + 8) * 40 + ks * 8 + tig + 4]);
            }
#pragma unroll
            for (int nt = 0; nt < 4; nt++) {
                uint32_t b0 = __float_as_uint(Bc[(ks * 8 + tig)     * 132 + n0w + nt * 8 + g]);
                uint32_t b1 = __float_as_uint(Bc[(ks * 8 + tig + 4) * 132 + n0w + nt * 8 + g]);
#pragma unroll
                for (int mt = 0; mt < 6; mt++) mma_tf32(acc[mt][nt], a[mt], b0, b1);
            }
        }
        __syncthreads();
    }

    // ---- epilogue: theta direct (transposed, rna); phi/g into smem ytile ----
    float* ytile = sm;   // 160 ch x 132 floats; staging buffers dead
    float* thb = d_theta + (size_t)b * HW * C8;
#pragma unroll
    for (int mt = 0; mt < 6; mt++)
#pragma unroll
        for (int nt = 0; nt < 4; nt++) {
            int pl = n0w + nt * 8 + tig * 2;
            int p  = p0 + pl;
            int c0 = m0w + mt * 16 + g;
            int c1 = c0 + 8;
            if (c0 < 32) {
                thb[(size_t)p * 32 + c0]       = tf32r(acc[mt][nt][0]);
                thb[(size_t)(p + 1) * 32 + c0] = tf32r(acc[mt][nt][1]);
                thb[(size_t)p * 32 + c1]       = tf32r(acc[mt][nt][2]);
                thb[(size_t)(p + 1) * 32 + c1] = tf32r(acc[mt][nt][3]);
            } else {
                ytile[(c0 - 32) * 132 + pl]     = acc[mt][nt][0];
                ytile[(c0 - 32) * 132 + pl + 1] = acc[mt][nt][1];
                ytile[(c1 - 32) * 132 + pl]     = acc[mt][nt][2];
                ytile[(c1 - 32) * 132 + pl + 1] = acc[mt][nt][3];
            }
        }
    __syncthreads();

    const int m0 = (p0 >> 2);
#pragma unroll
    for (int i = 0; i < 20; i++) {
        int idx = tid + i * 256;
        int ch = idx >> 5, wp = idx & 31;
        const float* r0 = &ytile[ch * 132 + wp * 2];
        float v = fmaxf(fmaxf(r0[0], r0[1]), fmaxf(r0[64], r0[65]));
        if (ch < 32)
            d_phi[((size_t)b * 32 + ch) * MPOOL + m0 + wp] = tf32r(v);
        else
            d_gT[((size_t)b * C2 + (ch - 32)) * MPOOL + m0 + wp] = __float2bfloat16(v);
    }
}

// =============================================================================
// K2: fused flash attention (no online max), 3-stage cp.async pipeline.
// 256 threads, 8 warps; warp: 16q x 128d.  (round-5 best)
// =============================================================================
#define KB       64
#define NTILE    (MPOOL / KB)        // 16
#define PH_STR   68
#define G_STR    72
#define PH_BYTES (32 * PH_STR * 4)   // 8704
#define G_BYTES  (128 * G_STR * 2)   // 18432
#define K2_STAGE (PH_BYTES + G_BYTES)
#define K2_SMEM  (3 * K2_STAGE)      // 81408

__device__ __forceinline__ void attn_load_tile(uint32_t stage_base,
                                               const float* phb,
                                               const __nv_bfloat16* gTb,
                                               int mb, int tid) {
    const uint32_t ph_s = stage_base;
    const uint32_t g_s  = stage_base + PH_BYTES;
#pragma unroll
    for (int i = 0; i < 2; i++) {
        int c = tid + i * 256;
        int r = c >> 4, col = c & 15;
        cp16(ph_s + r * (PH_STR * 4) + col * 16,
             phb + (size_t)r * MPOOL + mb + col * 4);
    }
#pragma unroll
    for (int i = 0; i < 4; i++) {
        int c = tid + i * 256;
        int r = c >> 3, col = c & 7;
        cp16(g_s + r * (G_STR * 2) + col * 16,
             gTb + (size_t)r * MPOOL + mb + col * 8);
    }
}

__global__ __launch_bounds__(256, 1)
void attn_kernel() {
    extern __shared__ char smraw[];
    const uint32_t smem_u32 = (uint32_t)__cvta_generic_to_shared(smraw);

    const int b   = blockIdx.y, qt = blockIdx.x;
    const int tid = threadIdx.x;
    const int w   = tid >> 5, lane = tid & 31;
    const int g   = lane >> 2, tig = lane & 3;
    const int n0  = qt * 128 + w * 16;

    const float*         phb = d_phi + (size_t)b * 32 * MPOOL;
    const __nv_bfloat16* gTb = d_gT + (size_t)b * C2 * MPOOL;

    uint32_t at[4][4];
    {
        const float* th = d_theta + ((size_t)b * HW + n0) * 32;
#pragma unroll
        for (int ks = 0; ks < 4; ks++) {
            at[ks][0] = __float_as_uint(th[g * 32       + ks * 8 + tig]);
            at[ks][1] = __float_as_uint(th[(g + 8) * 32 + ks * 8 + tig]);
            at[ks][2] = __float_as_uint(th[g * 32       + ks * 8 + tig + 4]);
            at[ks][3] = __float_as_uint(th[(g + 8) * 32 + ks * 8 + tig + 4]);
        }
    }

    float O[16][4];
#pragma unroll
    for (int df = 0; df < 16; df++)
#pragma unroll
        for (int j = 0; j < 4; j++) O[df][j] = 0.f;
    float lsum0 = 0.f, lsum1 = 0.f;

    attn_load_tile(smem_u32, phb, gTb, 0, tid);
    cp_commit();
    attn_load_tile(smem_u32 + K2_STAGE, phb, gTb, KB, tid);
    cp_commit();

    for (int kb = 0; kb < NTILE; kb++) {
        const int cur = kb % 3;
        if (kb + 2 < NTILE) {
            attn_load_tile(smem_u32 + ((kb + 2) % 3) * K2_STAGE,
                           phb, gTb, (kb + 2) * KB, tid);
            cp_commit();
            cp_wait<2>();
        } else if (kb + 1 < NTILE) {
            cp_wait<1>();
        } else {
            cp_wait<0>();
        }
        __syncthreads();

        const uint32_t phc = smem_u32 + cur * K2_STAGE;
        const uint32_t gc  = phc + PH_BYTES;

        float S[8][4];
#pragma unroll
        for (int nf = 0; nf < 8; nf++)
            S[nf][0] = S[nf][1] = S[nf][2] = S[nf][3] = 0.f;
#pragma unroll
        for (int ks = 0; ks < 4; ks++) {
#pragma unroll
            for (int nf = 0; nf < 8; nf++) {
                uint32_t b0, b1;
                uint32_t a0 = phc + ((ks * 8 + tig) * PH_STR + nf * 8 + g) * 4;
                asm volatile("ld.shared.b32 %0, [%1];" : "=r"(b0) : "r"(a0));
                asm volatile("ld.shared.b32 %0, [%1];" : "=r"(b1) : "r"(a0 + 4 * PH_STR * 4));
                mma_tf32(S[nf], at[ks], b0, b1);
            }
        }

#pragma unroll
        for (int nf = 0; nf < 8; nf++) {
            S[nf][0] = ex2(S[nf][0] * LOG2E);
            S[nf][1] = ex2(S[nf][1] * LOG2E);
            S[nf][2] = ex2(S[nf][2] * LOG2E);
            S[nf][3] = ex2(S[nf][3] * LOG2E);
            lsum0 += S[nf][0] + S[nf][1];
            lsum1 += S[nf][2] + S[nf][3];
        }

        uint32_t P[4][4];
#pragma unroll
        for (int kf = 0; kf < 4; kf++) {
            P[kf][0] = pack_bf16(S[2 * kf][0],     S[2 * kf][1]);
            P[kf][1] = pack_bf16(S[2 * kf][2],     S[2 * kf][3]);
            P[kf][2] = pack_bf16(S[2 * kf + 1][0], S[2 * kf + 1][1]);
            P[kf][3] = pack_bf16(S[2 * kf + 1][2], S[2 * kf + 1][3]);
        }

#pragma unroll
        for (int pair = 0; pair < 2; pair++) {
#pragma unroll
            for (int df = 0; df < 16; df++) {
                uint32_t r0, r1, r2, r3;
                uint32_t addr = gc +
                    ((df * 8 + (lane & 7)) * G_STR + pair * 32 + (lane >> 3) * 8) * 2;
                ldsm_x4(r0, r1, r2, r3, addr);
                mma_bf16(O[df], P[2 * pair],     r0, r1);
                mma_bf16(O[df], P[2 * pair + 1], r2, r3);
            }
        }
        __syncthreads();
    }

    lsum0 += __shfl_xor_sync(0xffffffffu, lsum0, 1);
    lsum0 += __shfl_xor_sync(0xffffffffu, lsum0, 2);
    lsum1 += __shfl_xor_sync(0xffffffffu, lsum1, 1);
    lsum1 += __shfl_xor_sync(0xffffffffu, lsum1, 2);
    const float i0 = 1.f / lsum0, i1 = 1.f / lsum1;

    __nv_bfloat16* agb = d_ag + ((size_t)b * HW + n0) * C2;
#pragma unroll
    for (int df = 0; df < 16; df++) {
        uint32_t v0 = pack_bf16(O[df][0] * i0, O[df][1] * i0);
        uint32_t v1 = pack_bf16(O[df][2] * i1, O[df][3] * i1);
        *reinterpret_cast<uint32_t*>(&agb[g * C2 + df * 8 + tig * 2])       = v0;
        *reinterpret_cast<uint32_t*>(&agb[(g + 8) * C2 + df * 8 + tig * 2]) = v1;
    }
}

// =============================================================================
// K3: out = sigma * (w_final @ attn_g^T) + x
// tile 64co x 64p, 8 warps (2m x 4n), warp tile 32x16, 4 CTAs/SM.
// =============================================================================
#define F_STR    136
#define F_ABYTES (64 * F_STR * 2)       // 17408
#define F_BBYTES (64 * F_STR * 2)       // 17408
#define F_SMEM   (F_ABYTES + F_BBYTES)  // 34816

__global__ __launch_bounds__(256, 4)
void final_kernel(const float* __restrict__ x,
                  const float* __restrict__ sigp,
                  float* __restrict__ out) {
    extern __shared__ char smraw[];
    const uint32_t as_u = (uint32_t)__cvta_generic_to_shared(smraw);
    const uint32_t bs_u = as_u + F_ABYTES;

    const int b   = blockIdx.y;
    const int co0 = (blockIdx.x & 3) * 64;
    const int p0  = (blockIdx.x >> 2) * 64;
    const int tid = threadIdx.x;
    const int w   = tid >> 5, lane = tid & 31;
    const int g   = lane >> 2, tig = lane & 3;
    const int wm  = w >> 2, wn = w & 3;
    const int cw  = wm * 32, pw = wn * 16;

    // stage A (wfb rows co0..co0+63) and B (ag rows p0..p0+63)
    const __nv_bfloat16* wfb = d_wfb + (size_t)co0 * C2;
#pragma unroll
    for (int i = 0; i < 4; i++) {
        int c = tid + i * 256;
        int r = c >> 4, q = c & 15;
        cp16(as_u + (r * F_STR + q * 8) * 2, wfb + (size_t)r * C2 + q * 8);
    }
    const __nv_bfloat16* agb = d_ag + ((size_t)b * HW + p0) * C2;
#pragma unroll
    for (int i = 0; i < 4; i++) {
        int c = tid + i * 256;
        int j = c >> 4, q = c & 15;
        cp16(bs_u + (j * F_STR + q * 8) * 2, agb + (size_t)j * C2 + q * 8);
    }
    cp_commit();
    cp_wait<0>();
    __syncthreads();

    float acc[2][2][4];
#pragma unroll
    for (int mt = 0; mt < 2; mt++)
#pragma unroll
        for (int nt = 0; nt < 2; nt++)
#pragma unroll
            for (int j = 0; j < 4; j++) acc[mt][nt][j] = 0.f;

#pragma unroll
    for (int k16 = 0; k16 < 8; k16++) {
        uint32_t a[2][4];
#pragma unroll
        for (int mt = 0; mt < 2; mt++) {
            uint32_t addr = as_u +
                ((cw + mt * 16 + (lane & 15)) * F_STR + k16 * 16 + (lane >> 4) * 8) * 2;
            ldsm_x4(a[mt][0], a[mt][1], a[mt][2], a[mt][3], addr);
        }
        uint32_t bq[2][2];
#pragma unroll
        for (int nt = 0; nt < 2; nt++) {
            uint32_t addr = bs_u +
                ((pw + nt * 8 + (lane & 7)) * F_STR + k16 * 16 + ((lane >> 3) & 1) * 8) * 2;
            ldsm_x2(bq[nt][0], bq[nt][1], addr);
        }
#pragma unroll
        for (int nt = 0; nt < 2; nt++)
#pragma unroll
            for (int mt = 0; mt < 2; mt++)
                mma_bf16(acc[mt][nt], a[mt], bq[nt][0], bq[nt][1]);
    }

    const float sig = *sigp;
#pragma unroll
    for (int mt = 0; mt < 2; mt++)
#pragma unroll
        for (int nt = 0; nt < 2; nt++) {
            int co = co0 + cw + mt * 16 + g;
            int p  = p0 + pw + nt * 8 + tig * 2;
            {
                size_t off = ((size_t)b * 256 + co) * HW + p;
                float2 xv = *reinterpret_cast<const float2*>(&x[off]);
                float2 ov = make_float2(sig * acc[mt][nt][0] + xv.x,
                                        sig * acc[mt][nt][1] + xv.y);
                *reinterpret_cast<float2*>(&out[off]) = ov;
            }
            {
                size_t off = ((size_t)b * 256 + co + 8) * HW + p;
                float2 xv = *reinterpret_cast<const float2*>(&x[off]);
                float2 ov = make_float2(sig * acc[mt][nt][2] + xv.x,
                                        sig * acc[mt][nt][3] + xv.y);
                *reinterpret_cast<float2*>(&out[off]) = ov;
            }
        }
}

// =============================================================================
extern "C" void kernel_launch(void* const* d_in, const int* in_sizes, int n_in,
                              void* d_out, int out_size) {
    (void)in_sizes; (void)n_in; (void)out_size;
    const float* x    = (const float*)d_in[0];
    const float* wth  = (const float*)d_in[1];
    const float* wph  = (const float*)d_in[2];
    const float* wg   = (const float*)d_in[3];
    const float* wf   = (const float*)d_in[4];
    const float* sig  = (const float*)d_in[5];
    float*       out  = (float*)d_out;

    cudaFuncSetAttribute(proj_kernel,
                         cudaFuncAttributeMaxDynamicSharedMemorySize, PJ_SMEM_B);
    cudaFuncSetAttribute(attn_kernel,
                         cudaFuncAttributeMaxDynamicSharedMemorySize, K2_SMEM);
    cudaFuncSetAttribute(final_kernel,
                         cudaFuncAttributeMaxDynamicSharedMemorySize, F_SMEM);

    wfconv_kernel<<<(C_IN * C2) / 256, 256>>>(wf);
    proj_kernel<<<dim3(32, 16), 256, PJ_SMEM_B>>>(x, wth, wph, wg);
    attn_kernel<<<dim3(32, 16), 256, K2_SMEM>>>();
    final_kernel<<<dim3(256, 16), 256, F_SMEM>>>(x, sig, out);
}

// round 8
// speedup vs baseline: 1.2327x; 1.0148x over previous
#include <cuda_runtime.h>
#include <cuda_bf16.h>
#include <cstdint>

#define BATCH 16
#define C_IN  256
#define HW    4096
#define C8    32
#define C2    128
#define MPOOL 1024
#define CPROJ 192   // 32 theta + 32 phi + 128 g

// ---------------- scratch (device globals; no allocation allowed) ----------
__device__ float         d_theta[BATCH * HW * C8];     // [b][n][k]  (tf32-rounded)
__device__ float         d_phi[BATCH * C8 * MPOOL];    // [b][k][m]  (tf32-rounded)
__device__ __nv_bfloat16 d_gT[BATCH * C2 * MPOOL];     // [b][d][m]
__device__ __nv_bfloat16 d_wfb[C_IN * C2];             // bf16 copy of w_final

// ---------------- helpers ---------------------------------------------------
__device__ __forceinline__ float tf32r(float f) {
    uint32_t u;
    asm("cvt.rna.tf32.f32 %0, %1;" : "=r"(u) : "f"(f));
    return __uint_as_float(u);
}

__device__ __forceinline__ float ex2(float x) {
    float y;
    asm("ex2.approx.ftz.f32 %0, %1;" : "=f"(y) : "f"(x));
    return y;
}

__device__ __forceinline__ void mma_tf32(float* d, const uint32_t* a,
                                         uint32_t b0, uint32_t b1) {
    asm volatile(
        "mma.sync.aligned.m16n8k8.row.col.f32.tf32.tf32.f32 "
        "{%0,%1,%2,%3}, {%4,%5,%6,%7}, {%8,%9}, {%0,%1,%2,%3};"
        : "+f"(d[0]), "+f"(d[1]), "+f"(d[2]), "+f"(d[3])
        : "r"(a[0]), "r"(a[1]), "r"(a[2]), "r"(a[3]), "r"(b0), "r"(b1));
}

__device__ __forceinline__ void mma_bf16(float* d, const uint32_t* a,
                                         uint32_t b0, uint32_t b1) {
    asm volatile(
        "mma.sync.aligned.m16n8k16.row.col.f32.bf16.bf16.f32 "
        "{%0,%1,%2,%3}, {%4,%5,%6,%7}, {%8,%9}, {%0,%1,%2,%3};"
        : "+f"(d[0]), "+f"(d[1]), "+f"(d[2]), "+f"(d[3])
        : "r"(a[0]), "r"(a[1]), "r"(a[2]), "r"(a[3]), "r"(b0), "r"(b1));
}

__device__ __forceinline__ void ldsm_x4(uint32_t& r0, uint32_t& r1,
                                        uint32_t& r2, uint32_t& r3, uint32_t a) {
    asm volatile("ldmatrix.sync.aligned.m8n8.x4.shared.b16 {%0,%1,%2,%3}, [%4];"
                 : "=r"(r0), "=r"(r1), "=r"(r2), "=r"(r3) : "r"(a));
}
__device__ __forceinline__ void ldsm_x2(uint32_t& r0, uint32_t& r1, uint32_t a) {
    asm volatile("ldmatrix.sync.aligned.m8n8.x2.shared.b16 {%0,%1}, [%2];"
                 : "=r"(r0), "=r"(r1) : "r"(a));
}

__device__ __forceinline__ uint32_t pack_bf16(float a, float b) {
    __nv_bfloat162 h = __floats2bfloat162_rn(a, b);
    return *reinterpret_cast<uint32_t*>(&h);
}

__device__ __forceinline__ void cp16(uint32_t smem, const void* g) {
    asm volatile("cp.async.cg.shared.global [%0], [%1], 16;\n"
                 :: "r"(smem), "l"(g));
}
__device__ __forceinline__ void cp_commit() {
    asm volatile("cp.async.commit_group;\n");
}
template <int N>
__device__ __forceinline__ void cp_wait() {
    asm volatile("cp.async.wait_group %0;\n" :: "n"(N));
}

#define LOG2E 1.4426950408889634f

// =============================================================================
// K0: w_final fp32 -> bf16 (one-time, tiny)
// =============================================================================
__global__ void wfconv_kernel(const float* __restrict__ wf) {
    int i = blockIdx.x * 256 + threadIdx.x;
    d_wfb[i] = __float2bfloat16(wf[i]);
}

// =============================================================================
// K1: projection GEMM + fused 2x2 maxpool, 3-stage cp.async pipeline.
// 256 threads, 8 warps (2m x 4n), warp tile 96x32. tf32 mma.  (round-7, proven)
// =============================================================================
#define PJ_A_F   (192 * 40)
#define PJ_B_F   (32 * 132)
#define PJ_STAGE (PJ_A_F + PJ_B_F)           // floats
#define PJ_SMEM_B (3 * PJ_STAGE * 4)         // 142848 bytes (>= ytile 160*132*4)

__device__ __forceinline__ void proj_load(uint32_t a_s, uint32_t b_s,
                                          const float* wth, const float* wph,
                                          const float* wg, const float* xb,
                                          int kc, int p0, int tid) {
#pragma unroll
    for (int i = 0; i < 6; i++) {        // A: 192 rows x 32 floats
        int c = tid + i * 256;
        int r = c >> 3, q = c & 7;
        const float* src = (r < 32) ? wth + r * 256
                        : (r < 64) ? wph + (r - 32) * 256
                                   : wg + (r - 64) * 256;
        cp16(a_s + (r * 40 + q * 4) * 4, src + kc * 32 + q * 4);
    }
#pragma unroll
    for (int i = 0; i < 4; i++) {        // B: 32 rows x 128 floats
        int c = tid + i * 256;
        int kk = c >> 5, j4 = c & 31;
        cp16(b_s + (kk * 132 + j4 * 4) * 4,
             xb + (size_t)(kc * 32 + kk) * HW + p0 + j4 * 4);
    }
}

__global__ __launch_bounds__(256, 1)
void proj_kernel(const float* __restrict__ x,
                 const float* __restrict__ wth,
                 const float* __restrict__ wph,
                 const float* __restrict__ wg) {
    extern __shared__ float sm[];
    const uint32_t sm_u = (uint32_t)__cvta_generic_to_shared(sm);

    const int b   = blockIdx.y;
    const int p0  = blockIdx.x * 128;
    const int tid = threadIdx.x;
    const int w   = tid >> 5, lane = tid & 31;
    const int g   = lane >> 2, tig = lane & 3;
    const int wm  = w >> 2, wn = w & 3;
    const int m0w = wm * 96, n0w = wn * 32;

    float acc[6][4][4];
#pragma unroll
    for (int mt = 0; mt < 6; mt++)
#pragma unroll
        for (int nt = 0; nt < 4; nt++)
#pragma unroll
            for (int j = 0; j < 4; j++) acc[mt][nt][j] = 0.f;

    const float* xb = x + (size_t)b * C_IN * HW;

    proj_load(sm_u, sm_u + PJ_A_F * 4, wth, wph, wg, xb, 0, p0, tid);
    cp_commit();
    proj_load(sm_u + PJ_STAGE * 4, sm_u + (PJ_STAGE + PJ_A_F) * 4,
              wth, wph, wg, xb, 1, p0, tid);
    cp_commit();

    for (int kc = 0; kc < 8; kc++) {
        const int cur = kc % 3;
        if (kc + 2 < 8) {
            const int nst = (kc + 2) % 3;
            proj_load(sm_u + nst * PJ_STAGE * 4,
                      sm_u + (nst * PJ_STAGE + PJ_A_F) * 4,
                      wth, wph, wg, xb, kc + 2, p0, tid);
            cp_commit();
            cp_wait<2>();
        } else if (kc + 1 < 8) {
            cp_wait<1>();
        } else {
            cp_wait<0>();
        }
        __syncthreads();

        const float* Ac = sm + cur * PJ_STAGE;
        const float* Bc = sm + cur * PJ_STAGE + PJ_A_F;
#pragma unroll
        for (int ks = 0; ks < 4; ks++) {
            uint32_t a[6][4];
#pragma unroll
            for (int mt = 0; mt < 6; mt++) {
                int r = m0w + mt * 16;
                a[mt][0] = __float_as_uint(Ac[(r + g)     * 40 + ks * 8 + tig]);
                a[mt][1] = __float_as_uint(Ac[(r + g + 8) * 40 + ks * 8 + tig]);
                a[mt][2] = __float_as_uint(Ac[(r + g)     * 40 + ks * 8 + tig + 4]);
                a[mt][3] = __float_as_uint(Ac[(r + g + 8) * 40 + ks * 8 + tig + 4]);
            }
#pragma unroll
            for (int nt = 0; nt < 4; nt++) {
                uint32_t b0 = __float_as_uint(Bc[(ks * 8 + tig)     * 132 + n0w + nt * 8 + g]);
                uint32_t b1 = __float_as_uint(Bc[(ks * 8 + tig + 4) * 132 + n0w + nt * 8 + g]);
#pragma unroll
                for (int mt = 0; mt < 6; mt++) mma_tf32(acc[mt][nt], a[mt], b0, b1);
            }
        }
        __syncthreads();
    }

    // ---- epilogue: theta direct (transposed, rna); phi/g into smem ytile ----
    float* ytile = sm;   // 160 ch x 132 floats; staging buffers dead
    float* thb = d_theta + (size_t)b * HW * C8;
#pragma unroll
    for (int mt = 0; mt < 6; mt++)
#pragma unroll
        for (int nt = 0; nt < 4; nt++) {
            int pl = n0w + nt * 8 + tig * 2;
            int p  = p0 + pl;
            int c0 = m0w + mt * 16 + g;
            int c1 = c0 + 8;
            if (c0 < 32) {
                thb[(size_t)p * 32 + c0]       = tf32r(acc[mt][nt][0]);
                thb[(size_t)(p + 1) * 32 + c0] = tf32r(acc[mt][nt][1]);
                thb[(size_t)p * 32 + c1]       = tf32r(acc[mt][nt][2]);
                thb[(size_t)(p + 1) * 32 + c1] = tf32r(acc[mt][nt][3]);
            } else {
                ytile[(c0 - 32) * 132 + pl]     = acc[mt][nt][0];
                ytile[(c0 - 32) * 132 + pl + 1] = acc[mt][nt][1];
                ytile[(c1 - 32) * 132 + pl]     = acc[mt][nt][2];
                ytile[(c1 - 32) * 132 + pl + 1] = acc[mt][nt][3];
            }
        }
    __syncthreads();

    const int m0 = (p0 >> 2);
#pragma unroll
    for (int i = 0; i < 20; i++) {
        int idx = tid + i * 256;
        int ch = idx >> 5, wp = idx & 31;
        const float* r0 = &ytile[ch * 132 + wp * 2];
        float v = fmaxf(fmaxf(r0[0], r0[1]), fmaxf(r0[64], r0[65]));
        if (ch < 32)
            d_phi[((size_t)b * 32 + ch) * MPOOL + m0 + wp] = tf32r(v);
        else
            d_gT[((size_t)b * C2 + (ch - 32)) * MPOOL + m0 + wp] = __float2bfloat16(v);
    }
}

// =============================================================================
// K2: fused flash attention + final 1x1 conv + residual.
// Mainloop: round-5 proven (256 thr, 8 warps, KB=64, 3-stage cp.async).
// Epilogue: O -> smem (bf16), out = sigma*(wf @ O^T) + x written directly.
// =============================================================================
#define KB       64
#define NTILE    (MPOOL / KB)        // 16
#define PH_STR   68
#define G_STR    72
#define PH_BYTES (32 * PH_STR * 4)   // 8704
#define G_BYTES  (128 * G_STR * 2)   // 18432
#define K2_STAGE (PH_BYTES + G_BYTES)
#define K2_STG_T (3 * K2_STAGE)      // 81408 (also holds Osm 128*136*2=34816)
#define WF_STR   136
#define WF_BYTES (256 * WF_STR * 2)  // 69632
#define K2_SMEM  (K2_STG_T + WF_BYTES)  // 151040

__device__ __forceinline__ void attn_load_tile(uint32_t stage_base,
                                               const float* phb,
                                               const __nv_bfloat16* gTb,
                                               int mb, int tid) {
    const uint32_t ph_s = stage_base;
    const uint32_t g_s  = stage_base + PH_BYTES;
#pragma unroll
    for (int i = 0; i < 2; i++) {
        int c = tid + i * 256;
        int r = c >> 4, col = c & 15;
        cp16(ph_s + r * (PH_STR * 4) + col * 16,
             phb + (size_t)r * MPOOL + mb + col * 4);
    }
#pragma unroll
    for (int i = 0; i < 4; i++) {
        int c = tid + i * 256;
        int r = c >> 3, col = c & 7;
        cp16(g_s + r * (G_STR * 2) + col * 16,
             gTb + (size_t)r * MPOOL + mb + col * 8);
    }
}

__global__ __launch_bounds__(256, 1)
void attn_kernel(const float* __restrict__ x,
                 const float* __restrict__ sigp,
                 float* __restrict__ out) {
    extern __shared__ char smraw[];
    const uint32_t smem_u32 = (uint32_t)__cvta_generic_to_shared(smraw);
    const uint32_t wf_u = smem_u32 + K2_STG_T;

    const int b   = blockIdx.y, qt = blockIdx.x;
    const int tid = threadIdx.x;
    const int w   = tid >> 5, lane = tid & 31;
    const int g   = lane >> 2, tig = lane & 3;
    const int n0  = qt * 128 + w * 16;

    const float*         phb = d_phi + (size_t)b * 32 * MPOOL;
    const __nv_bfloat16* gTb = d_gT + (size_t)b * C2 * MPOOL;

    // ---- prefetch wf (256x128 bf16 -> smem, stride 136) as oldest group ----
#pragma unroll
    for (int i = 0; i < 16; i++) {
        int c = tid + i * 256;
        int r = c >> 4, q = c & 15;
        cp16(wf_u + (r * WF_STR + q * 8) * 2, d_wfb + (size_t)r * C2 + q * 8);
    }
    cp_commit();

    uint32_t at[4][4];
    {
        const float* th = d_theta + ((size_t)b * HW + n0) * 32;
#pragma unroll
        for (int ks = 0; ks < 4; ks++) {
            at[ks][0] = __float_as_uint(th[g * 32       + ks * 8 + tig]);
            at[ks][1] = __float_as_uint(th[(g + 8) * 32 + ks * 8 + tig]);
            at[ks][2] = __float_as_uint(th[g * 32       + ks * 8 + tig + 4]);
            at[ks][3] = __float_as_uint(th[(g + 8) * 32 + ks * 8 + tig + 4]);
        }
    }

    float O[16][4];
#pragma unroll
    for (int df = 0; df < 16; df++)
#pragma unroll
        for (int j = 0; j < 4; j++) O[df][j] = 0.f;
    float lsum0 = 0.f, lsum1 = 0.f;

    attn_load_tile(smem_u32, phb, gTb, 0, tid);
    cp_commit();
    attn_load_tile(smem_u32 + K2_STAGE, phb, gTb, KB, tid);
    cp_commit();

    for (int kb = 0; kb < NTILE; kb++) {
        const int cur = kb % 3;
        if (kb + 2 < NTILE) {
            attn_load_tile(smem_u32 + ((kb + 2) % 3) * K2_STAGE,
                           phb, gTb, (kb + 2) * KB, tid);
            cp_commit();
            cp_wait<2>();
        } else if (kb + 1 < NTILE) {
            cp_wait<1>();
        } else {
            cp_wait<0>();
        }
        __syncthreads();

        const uint32_t phc = smem_u32 + cur * K2_STAGE;
        const uint32_t gc  = phc + PH_BYTES;

        float S[8][4];
#pragma unroll
        for (int nf = 0; nf < 8; nf++)
            S[nf][0] = S[nf][1] = S[nf][2] = S[nf][3] = 0.f;
#pragma unroll
        for (int ks = 0; ks < 4; ks++) {
#pragma unroll
            for (int nf = 0; nf < 8; nf++) {
                uint32_t b0, b1;
                uint32_t a0 = phc + ((ks * 8 + tig) * PH_STR + nf * 8 + g) * 4;
                asm volatile("ld.shared.b32 %0, [%1];" : "=r"(b0) : "r"(a0));
                asm volatile("ld.shared.b32 %0, [%1];" : "=r"(b1) : "r"(a0 + 4 * PH_STR * 4));
                mma_tf32(S[nf], at[ks], b0, b1);
            }
        }

#pragma unroll
        for (int nf = 0; nf < 8; nf++) {
            S[nf][0] = ex2(S[nf][0] * LOG2E);
            S[nf][1] = ex2(S[nf][1] * LOG2E);
            S[nf][2] = ex2(S[nf][2] * LOG2E);
            S[nf][3] = ex2(S[nf][3] * LOG2E);
            lsum0 += S[nf][0] + S[nf][1];
            lsum1 += S[nf][2] + S[nf][3];
        }

        uint32_t P[4][4];
#pragma unroll
        for (int kf = 0; kf < 4; kf++) {
            P[kf][0] = pack_bf16(S[2 * kf][0],     S[2 * kf][1]);
            P[kf][1] = pack_bf16(S[2 * kf][2],     S[2 * kf][3]);
            P[kf][2] = pack_bf16(S[2 * kf + 1][0], S[2 * kf + 1][1]);
            P[kf][3] = pack_bf16(S[2 * kf + 1][2], S[2 * kf + 1][3]);
        }

#pragma unroll
        for (int pair = 0; pair < 2; pair++) {
#pragma unroll
            for (int df = 0; df < 16; df++) {
                uint32_t r0, r1, r2, r3;
                uint32_t addr = gc +
                    ((df * 8 + (lane & 7)) * G_STR + pair * 32 + (lane >> 3) * 8) * 2;
                ldsm_x4(r0, r1, r2, r3, addr);
                mma_bf16(O[df], P[2 * pair],     r0, r1);
                mma_bf16(O[df], P[2 * pair + 1], r2, r3);
            }
        }
        __syncthreads();
    }

    // ---- normalize, O -> Osm (bf16, stride 136; staging area is dead) ----
    lsum0 += __shfl_xor_sync(0xffffffffu, lsum0, 1);
    lsum0 += __shfl_xor_sync(0xffffffffu, lsum0, 2);
    lsum1 += __shfl_xor_sync(0xffffffffu, lsum1, 1);
    lsum1 += __shfl_xor_sync(0xffffffffu, lsum1, 2);
    const float i0 = 1.f / lsum0, i1 = 1.f / lsum1;

    const uint32_t osm = smem_u32;
#pragma unroll
    for (int df = 0; df < 16; df++) {
        uint32_t v0 = pack_bf16(O[df][0] * i0, O[df][1] * i0);
        uint32_t v1 = pack_bf16(O[df][2] * i1, O[df][3] * i1);
        uint32_t a0 = osm + ((w * 16 + g) * WF_STR + df * 8 + tig * 2) * 2;
        asm volatile("st.shared.b32 [%0], %1;" :: "r"(a0), "r"(v0));
        asm volatile("st.shared.b32 [%0], %1;" :: "r"(a0 + 8 * WF_STR * 2), "r"(v1));
    }
    __syncthreads();

    // ---- final conv: out[256co x 128p] = sigma * wf @ Osm^T + x ----
    const float sig = *sigp;
    const int wm = w >> 1, wn = w & 1;
    const int cw = wm * 32, pw = wn * 64;

#pragma unroll
    for (int half = 0; half < 2; half++) {
        const int co0 = half * 128;
        float acc[2][8][4];
#pragma unroll
        for (int mt = 0; mt < 2; mt++)
#pragma unroll
            for (int nt = 0; nt < 8; nt++)
#pragma unroll
                for (int j = 0; j < 4; j++) acc[mt][nt][j] = 0.f;

#pragma unroll
        for (int k16 = 0; k16 < 8; k16++) {
            uint32_t a[2][4];
#pragma unroll
            for (int mt = 0; mt < 2; mt++) {
                uint32_t addr = wf_u +
                    ((co0 + cw + mt * 16 + (lane & 15)) * WF_STR + k16 * 16 + (lane >> 4) * 8) * 2;
                ldsm_x4(a[mt][0], a[mt][1], a[mt][2], a[mt][3], addr);
            }
            uint32_t bq[8][2];
#pragma unroll
            for (int nt = 0; nt < 8; nt++) {
                uint32_t addr = osm +
                    ((pw + nt * 8 + (lane & 7)) * WF_STR + k16 * 16 + ((lane >> 3) & 1) * 8) * 2;
                ldsm_x2(bq[nt][0], bq[nt][1], addr);
            }
#pragma unroll
            for (int nt = 0; nt < 8; nt++)
#pragma unroll
                for (int mt = 0; mt < 2; mt++)
                    mma_bf16(acc[mt][nt], a[mt], bq[nt][0], bq[nt][1]);
        }

#pragma unroll
        for (int mt = 0; mt < 2; mt++)
#pragma unroll
            for (int nt = 0; nt < 8; nt++) {
                int co = co0 + cw + mt * 16 + g;
                int p  = qt * 128 + pw + nt * 8 + tig * 2;
                {
                    size_t off = ((size_t)b * 256 + co) * HW + p;
                    float2 xv = *reinterpret_cast<const float2*>(&x[off]);
                    float2 ov = make_float2(sig * acc[mt][nt][0] + xv.x,
                                            sig * acc[mt][nt][1] + xv.y);
                    *reinterpret_cast<float2*>(&out[off]) = ov;
                }
                {
                    size_t off = ((size_t)b * 256 + co + 8) * HW + p;
                    float2 xv = *reinterpret_cast<const float2*>(&x[off]);
                    float2 ov = make_float2(sig * acc[mt][nt][2] + xv.x,
                                            sig * acc[mt][nt][3] + xv.y);
                    *reinterpret_cast<float2*>(&out[off]) = ov;
                }
            }
    }
}

// =============================================================================
extern "C" void kernel_launch(void* const* d_in, const int* in_sizes, int n_in,
                              void* d_out, int out_size) {
    (void)in_sizes; (void)n_in; (void)out_size;
    const float* x    = (const float*)d_in[0];
    const float* wth  = (const float*)d_in[1];
    const float* wph  = (const float*)d_in[2];
    const float* wg   = (const float*)d_in[3];
    const float* wf   = (const float*)d_in[4];
    const float* sig  = (const float*)d_in[5];
    float*       out  = (float*)d_out;

    cudaFuncSetAttribute(proj_kernel,
                         cudaFuncAttributeMaxDynamicSharedMemorySize, PJ_SMEM_B);
    cudaFuncSetAttribute(attn_kernel,
                         cudaFuncAttributeMaxDynamicSharedMemorySize, K2_SMEM);

    wfconv_kernel<<<(C_IN * C2) / 256, 256>>>(wf);
    proj_kernel<<<dim3(32, 16), 256, PJ_SMEM_B>>>(x, wth, wph, wg);
    attn_kernel<<<dim3(32, 16), 256, K2_SMEM>>>(x, sig, out);
}